// round 2
// baseline (speedup 1.0000x reference)
#include <cuda_runtime.h>
#include <cuda_bf16.h>

// Problem constants
#define BB 4
#define TT 512
#define CC 128     // IN_DIM / OUT_DIM
#define HH 256     // HIDDEN_DIM
#define NC 50      // NCLS
#define SCALE 0.0625f   // HIDDEN_DIM^-0.5
#define ROWS (BB*TT)    // 2048

// ---------------- scratch (device globals; no allocation allowed) -------------
__device__ float g_sj[ROWS];          // s_j per (b,s)
__device__ float g_a[ROWS];           // softmax'd adjacency row per batch (shared across t)
__device__ float g_pn[ROWS * NC];     // normalized pseudo labels
__device__ float g_h[ROWS * HH];      // relu(x@W1^T+b1)
__device__ float g_gpart[BB * 16 * HH]; // partial g accumulations
__device__ float g_h2[BB * CC];       // per-batch h2 = g@W2^T + b2
__device__ float g_losspart[128];     // per-block loss partials

// ---------------- K1: s_j + pseudo-label normalization ------------------------
__global__ void k_prep(const float* __restrict__ x, const float* __restrict__ pl,
                       const float* __restrict__ w_adj) {
    int row = blockIdx.x;
    int tid = threadIdx.x;   // 128 threads
    __shared__ float red[4];
    __shared__ float red2[4];

    float xv = x[row * CC + tid];
    float part = xv * w_adj[CC + tid];   // second half of w_adj
    #pragma unroll
    for (int o = 16; o; o >>= 1) part += __shfl_xor_sync(0xffffffffu, part, o);
    if ((tid & 31) == 0) red[tid >> 5] = part;

    float sq = 0.f, pv = 0.f;
    if (tid < NC) { pv = pl[row * NC + tid]; sq = pv * pv; }
    float s2 = sq;
    #pragma unroll
    for (int o = 16; o; o >>= 1) s2 += __shfl_xor_sync(0xffffffffu, s2, o);
    if ((tid & 31) == 0) red2[tid >> 5] = s2;
    __syncthreads();

    if (tid == 0) g_sj[row] = red[0] + red[1] + red[2] + red[3];
    if (tid < NC) {
        float norm = sqrtf(red2[0] + red2[1] + red2[2] + red2[3]);
        float inv = 1.f / fmaxf(norm, 1e-12f);
        g_pn[row * NC + tid] = pv * inv;
    }
}

// ---------------- K2: a[b,:] = softmax(s_j * scale) ---------------------------
__global__ void k_softmax_a() {
    int b = blockIdx.x, t = threadIdx.x;  // 512 threads
    __shared__ float red[16];
    float v = g_sj[b * TT + t];
    float m = v;
    #pragma unroll
    for (int o = 16; o; o >>= 1) m = fmaxf(m, __shfl_xor_sync(0xffffffffu, m, o));
    if ((t & 31) == 0) red[t >> 5] = m;
    __syncthreads();
    float bm = red[0];
    #pragma unroll
    for (int i = 1; i < 16; i++) bm = fmaxf(bm, red[i]);
    float e = __expf((v - bm) * SCALE);
    __syncthreads();
    float s = e;
    #pragma unroll
    for (int o = 16; o; o >>= 1) s += __shfl_xor_sync(0xffffffffu, s, o);
    if ((t & 31) == 0) red[t >> 5] = s;
    __syncthreads();
    float bs = 0.f;
    #pragma unroll
    for (int i = 0; i < 16; i++) bs += red[i];
    g_a[b * TT + t] = e / bs;
}

// ---------------- K3: h = relu(x @ W1^T + b1), tiled SGEMM --------------------
// M=2048, N=256, K=128. 64x64 tile, 256 threads, 4x4 microtile.
__global__ void k_hgemm(const float* __restrict__ x, const float* __restrict__ W1,
                        const float* __restrict__ b1) {
    __shared__ float As[16][65];
    __shared__ float Bs[16][65];
    int m0 = blockIdx.x * 64, n0 = blockIdx.y * 64;
    int tid = threadIdx.x;
    int ty = tid >> 4, tx = tid & 15;
    float c[4][4] = {};

    for (int k0 = 0; k0 < CC; k0 += 16) {
        int kk = tid & 15, rr = tid >> 4;
        #pragma unroll
        for (int i = 0; i < 4; i++) {
            As[kk][rr + 16 * i] = x[(m0 + rr + 16 * i) * CC + k0 + kk];
            Bs[kk][rr + 16 * i] = W1[(n0 + rr + 16 * i) * CC + k0 + kk];
        }
        __syncthreads();
        #pragma unroll
        for (int k = 0; k < 16; k++) {
            float av[4], bv[4];
            #pragma unroll
            for (int i = 0; i < 4; i++) { av[i] = As[k][ty + 16 * i]; bv[i] = Bs[k][tx + 16 * i]; }
            #pragma unroll
            for (int i = 0; i < 4; i++)
                #pragma unroll
                for (int j = 0; j < 4; j++) c[i][j] += av[i] * bv[j];
        }
        __syncthreads();
    }
    #pragma unroll
    for (int i = 0; i < 4; i++) {
        int m = m0 + ty + 16 * i;
        #pragma unroll
        for (int j = 0; j < 4; j++) {
            int n = n0 + tx + 16 * j;
            g_h[m * HH + n] = fmaxf(c[i][j] + b1[n], 0.f);
        }
    }
}

// ---------------- K4: partial g[b,:] = sum_s a[b,s]*h[b,s,:] ------------------
__global__ void k_gagg() {
    int b = blockIdx.x, sp = blockIdx.y, j = threadIdx.x;  // (4,16) x 256
    __shared__ float as[32];
    if (j < 32) as[j] = g_a[b * TT + sp * 32 + j];
    __syncthreads();
    float acc = 0.f;
    int base = (b * TT + sp * 32) * HH + j;
    #pragma unroll
    for (int s = 0; s < 32; s++) acc += as[s] * g_h[base + s * HH];
    g_gpart[(b * 16 + sp) * HH + j] = acc;
}

// ---------------- K5: h2[b,:] = g[b,:] @ W2^T + b2 ----------------------------
__global__ void k_h2(const float* __restrict__ W2, const float* __restrict__ b2) {
    int b = blockIdx.x, tid = threadIdx.x;  // 4 x 128
    __shared__ float g[HH];
    for (int k = tid; k < HH; k += 128) {
        float s = 0.f;
        #pragma unroll
        for (int sp = 0; sp < 16; sp++) s += g_gpart[(b * 16 + sp) * HH + k];
        g[k] = s;
    }
    __syncthreads();
    float acc = b2[tid];
    const float* w = W2 + tid * HH;
    #pragma unroll 8
    for (int k = 0; k < HH; k++) acc += g[k] * w[k];
    g_h2[b * CC + tid] = acc;
}

// ---------------- K6: pseudo softmax + MSE partials + adj broadcast write -----
#define TB 16
#define SC 32
__global__ void k_pseudo(const float* __restrict__ ptemp, float* __restrict__ adj_out) {
    int blk = blockIdx.x;              // 128 blocks = 4 batches x 32 row tiles
    int b = blk >> 5;
    int r0 = (blk & 31) * TB;
    int tid = threadIdx.x;             // 256 threads

    __shared__ float a_sh[TT];
    __shared__ float pt[TB][51];
    __shared__ float sb[SC][51];
    __shared__ float ps[TB][TT];
    __shared__ float wloss[8];

    for (int i = tid; i < TT; i += 256) a_sh[i] = g_a[b * TT + i];
    for (int i = tid; i < TB * NC; i += 256) {
        int r = i / NC, c = i % NC;
        pt[r][c] = g_pn[(b * TT + r0 + r) * NC + c];
    }
    __syncthreads();

    for (int s0 = 0; s0 < TT; s0 += SC) {
        for (int i = tid; i < SC * NC; i += 256) {
            int s = i / NC, c = i % NC;
            sb[s][c] = g_pn[(b * TT + s0 + s) * NC + c];
        }
        __syncthreads();
        #pragma unroll
        for (int p = tid; p < TB * SC; p += 256) {
            int r = p >> 5, s = p & 31;
            float acc = 0.f;
            #pragma unroll
            for (int c = 0; c < NC; c++) acc += pt[r][c] * sb[s][c];
            ps[r][s0 + s] = acc;
        }
        __syncthreads();
    }

    float invtemp = 1.f / fmaxf(fabsf(ptemp[0]), 0.01f);
    int wid = tid >> 5, lane = tid & 31;
    float lacc = 0.f;
    #pragma unroll
    for (int rr = 0; rr < 2; rr++) {
        int r = wid * 2 + rr;
        float m = -1e30f;
        for (int i = lane; i < TT; i += 32) m = fmaxf(m, ps[r][i] * invtemp);
        #pragma unroll
        for (int o = 16; o; o >>= 1) m = fmaxf(m, __shfl_xor_sync(0xffffffffu, m, o));
        float ssum = 0.f;
        for (int i = lane; i < TT; i += 32) {
            float e = __expf(ps[r][i] * invtemp - m);
            ps[r][i] = e;
            ssum += e;
        }
        #pragma unroll
        for (int o = 16; o; o >>= 1) ssum += __shfl_xor_sync(0xffffffffu, ssum, o);
        float inv = 1.f / ssum;
        for (int i = lane; i < TT; i += 32) {
            float d = ps[r][i] * inv - a_sh[i];
            lacc += d * d;
        }
    }
    #pragma unroll
    for (int o = 16; o; o >>= 1) lacc += __shfl_xor_sync(0xffffffffu, lacc, o);
    if (lane == 0) wloss[wid] = lacc;
    __syncthreads();
    if (tid == 0) {
        float s = 0.f;
        #pragma unroll
        for (int i = 0; i < 8; i++) s += wloss[i];
        g_losspart[blk] = s;
    }
    // adj output: every row of this tile is a_sh (rank-1 logits => rows identical)
    for (int i = tid; i < TB * TT; i += 256) {
        int r = i >> 9, s = i & 511;
        adj_out[((b * TT) + r0 + r) * TT + s] = a_sh[s];
    }
}

// ---------------- K7: y = h2[b] + x, LayerNorm, write out ---------------------
__global__ void k_epi(const float* __restrict__ x, const float* __restrict__ gamma,
                      const float* __restrict__ beta, float* __restrict__ out) {
    int row = blockIdx.x, j = threadIdx.x;  // 2048 x 128
    int b = row >> 9;
    __shared__ float red[4];
    float y = g_h2[b * CC + j] + x[row * CC + j];
    float s = y;
    #pragma unroll
    for (int o = 16; o; o >>= 1) s += __shfl_xor_sync(0xffffffffu, s, o);
    if ((j & 31) == 0) red[j >> 5] = s;
    __syncthreads();
    float mu = (red[0] + red[1] + red[2] + red[3]) * (1.f / 128.f);
    float d = y - mu;
    __syncthreads();
    float s2 = d * d;
    #pragma unroll
    for (int o = 16; o; o >>= 1) s2 += __shfl_xor_sync(0xffffffffu, s2, o);
    if ((j & 31) == 0) red[j >> 5] = s2;
    __syncthreads();
    float var = (red[0] + red[1] + red[2] + red[3]) * (1.f / 128.f);
    out[row * CC + j] = d * rsqrtf(var + 1e-5f) * gamma[j] + beta[j];
}

// ---------------- K8: finalize supervision loss -------------------------------
__global__ void k_loss(const float* __restrict__ supw, float* __restrict__ loss_out) {
    int t = threadIdx.x;  // 128
    __shared__ float red[4];
    float v = g_losspart[t];
    #pragma unroll
    for (int o = 16; o; o >>= 1) v += __shfl_xor_sync(0xffffffffu, v, o);
    if ((t & 31) == 0) red[t >> 5] = v;
    __syncthreads();
    if (t == 0) {
        float total = red[0] + red[1] + red[2] + red[3];
        float mse = total * (1.f / (float)(BB * TT * TT));
        float sig = 1.f / (1.f + __expf(-supw[0]));
        loss_out[0] = mse * sig;
    }
}

// ---------------- launch ------------------------------------------------------
extern "C" void kernel_launch(void* const* d_in, const int* in_sizes, int n_in,
                              void* d_out, int out_size) {
    const float* x     = (const float*)d_in[0];
    const float* pl    = (const float*)d_in[1];
    const float* W1    = (const float*)d_in[2];
    const float* b1    = (const float*)d_in[3];
    const float* W2    = (const float*)d_in[4];
    const float* b2    = (const float*)d_in[5];
    const float* w_adj = (const float*)d_in[6];
    // d_in[7] = b_adj: cancels inside the row softmax (rank-1 logits), unused
    const float* ptemp = (const float*)d_in[8];
    const float* supw  = (const float*)d_in[9];
    const float* gamma = (const float*)d_in[10];
    const float* beta  = (const float*)d_in[11];

    float* out      = (float*)d_out;
    float* adj_out  = out + BB * TT * CC;                 // 262144
    float* loss_out = adj_out + BB * TT * TT;             // +1048576

    k_prep<<<ROWS, 128>>>(x, pl, w_adj);
    k_softmax_a<<<BB, TT>>>();
    k_hgemm<<<dim3(ROWS / 64, HH / 64), 256>>>(x, W1, b1);
    k_gagg<<<dim3(BB, 16), 256>>>();
    k_h2<<<BB, CC>>>(W2, b2);
    k_pseudo<<<128, 256>>>(ptemp, adj_out);
    k_epi<<<ROWS, CC>>>(x, gamma, beta, out);
    k_loss<<<1, 128>>>(supw, loss_out);
}

// round 3
// speedup vs baseline: 1.0270x; 1.0270x over previous
#include <cuda_runtime.h>
#include <cuda_bf16.h>

// Problem constants
#define BB 4
#define TT 512
#define CC 128     // IN_DIM / OUT_DIM
#define HH 256     // HIDDEN_DIM
#define NC 50      // NCLS
#define SCALE 0.0625f   // HIDDEN_DIM^-0.5
#define ROWS (BB*TT)    // 2048

// ---------------- scratch (device globals; no allocation allowed) -------------
__device__ float g_sj[ROWS];            // s_j per (b,s)
__device__ float g_pn[ROWS * NC];       // normalized pseudo labels
__device__ float g_gpart[BB * 8 * HH];  // per-(batch,mtile) partial aggregations
__device__ float g_h2[BB * CC];         // per-batch h2 = g@W2^T + b2
__device__ float g_losspart[128];       // per-block loss partials

// ---------------- K1: s_j + pseudo-label normalization ------------------------
__global__ void k_prep(const float* __restrict__ x, const float* __restrict__ pl,
                       const float* __restrict__ w_adj) {
    int row = blockIdx.x;
    int tid = threadIdx.x;   // 128 threads
    __shared__ float red[4];
    __shared__ float red2[4];

    float xv = x[row * CC + tid];
    float part = xv * w_adj[CC + tid];   // second half of w_adj
    #pragma unroll
    for (int o = 16; o; o >>= 1) part += __shfl_xor_sync(0xffffffffu, part, o);
    if ((tid & 31) == 0) red[tid >> 5] = part;

    float sq = 0.f, pv = 0.f;
    if (tid < NC) { pv = pl[row * NC + tid]; sq = pv * pv; }
    float s2 = sq;
    #pragma unroll
    for (int o = 16; o; o >>= 1) s2 += __shfl_xor_sync(0xffffffffu, s2, o);
    if ((tid & 31) == 0) red2[tid >> 5] = s2;
    __syncthreads();

    if (tid == 0) g_sj[row] = red[0] + red[1] + red[2] + red[3];
    if (tid < NC) {
        float norm = sqrtf(red2[0] + red2[1] + red2[2] + red2[3]);
        float inv = 1.f / fmaxf(norm, 1e-12f);
        g_pn[row * NC + tid] = pv * inv;
    }
}

// ------- in-block softmax helper: stats over g_sj[b*TT .. +512), 256 threads --
__device__ __forceinline__ void softmax_stats(int b, int tid, float* sred,
                                              float& bmax, float& bsum,
                                              float& v0, float& v1) {
    int lane = tid & 31, wid = tid >> 5;
    v0 = g_sj[b * TT + tid];
    v1 = g_sj[b * TT + 256 + tid];
    float m = fmaxf(v0, v1);
    #pragma unroll
    for (int o = 16; o; o >>= 1) m = fmaxf(m, __shfl_xor_sync(0xffffffffu, m, o));
    if (lane == 0) sred[wid] = m;
    __syncthreads();
    bmax = sred[0];
    #pragma unroll
    for (int i = 1; i < 8; i++) bmax = fmaxf(bmax, sred[i]);
    __syncthreads();
    float e = __expf((v0 - bmax) * SCALE) + __expf((v1 - bmax) * SCALE);
    #pragma unroll
    for (int o = 16; o; o >>= 1) e += __shfl_xor_sync(0xffffffffu, e, o);
    if (lane == 0) sred[wid] = e;
    __syncthreads();
    bsum = 0.f;
    #pragma unroll
    for (int i = 0; i < 8; i++) bsum += sred[i];
    __syncthreads();
}

// ---------------- K2: fused h-GEMM + a-weighted aggregation -------------------
// grid (32 mtiles, 4 ntiles) x 256 thr. Each block: 64 rows x 64 cols of
// h = relu(x@W1^T + b1), then reduces sum_m a[m]*h[m,n] -> g_gpart.
__global__ void k_gemm_agg(const float* __restrict__ x, const float* __restrict__ W1,
                           const float* __restrict__ b1) {
    __shared__ float As[16][65];
    __shared__ float Bs[16][65];
    __shared__ float sred[8];
    __shared__ float a_sh[64];

    int mt = blockIdx.x;       // global 64-row tile, 0..31
    int b  = mt >> 3;
    int m0 = mt * 64;
    int n0 = blockIdx.y * 64;
    int tid = threadIdx.x;
    int ty = tid >> 4, tx = tid & 15;

    // recompute softmax over this batch (fixed order => deterministic)
    float bmax, bsum, v0, v1;
    softmax_stats(b, tid, sred, bmax, bsum, v0, v1);
    if (tid < 64) a_sh[tid] = __expf((g_sj[m0 + tid] - bmax) * SCALE) / bsum;
    // (a_sh consumed only after the k-loop's __syncthreads barriers)

    float c[4][4] = {};
    for (int k0 = 0; k0 < CC; k0 += 16) {
        int kk = tid & 15, rr = tid >> 4;
        #pragma unroll
        for (int i = 0; i < 4; i++) {
            As[kk][rr + 16 * i] = x[(m0 + rr + 16 * i) * CC + k0 + kk];
            Bs[kk][rr + 16 * i] = W1[(n0 + rr + 16 * i) * CC + k0 + kk];
        }
        __syncthreads();
        #pragma unroll
        for (int k = 0; k < 16; k++) {
            float av[4], bv[4];
            #pragma unroll
            for (int i = 0; i < 4; i++) { av[i] = As[k][ty + 16 * i]; bv[i] = Bs[k][tx + 16 * i]; }
            #pragma unroll
            for (int i = 0; i < 4; i++)
                #pragma unroll
                for (int j = 0; j < 4; j++) c[i][j] += av[i] * bv[j];
        }
        __syncthreads();
    }

    // epilogue: gl[j] = sum_i a[m] * relu(c + b1)
    float b1v[4], gl[4] = {};
    #pragma unroll
    for (int j = 0; j < 4; j++) b1v[j] = b1[n0 + tx + 16 * j];
    #pragma unroll
    for (int i = 0; i < 4; i++) {
        float av = a_sh[ty + 16 * i];
        #pragma unroll
        for (int j = 0; j < 4; j++)
            gl[j] += av * fmaxf(c[i][j] + b1v[j], 0.f);
    }
    // reduce over ty (16 groups), reusing As
    #pragma unroll
    for (int j = 0; j < 4; j++) As[ty][tx + 16 * j] = gl[j];
    __syncthreads();
    #pragma unroll
    for (int st = 8; st; st >>= 1) {
        if (ty < st) {
            #pragma unroll
            for (int j = 0; j < 4; j++) As[ty][tx + 16 * j] += As[ty + st][tx + 16 * j];
        }
        __syncthreads();
    }
    if (ty == 0) {
        #pragma unroll
        for (int j = 0; j < 4; j++)
            g_gpart[mt * HH + n0 + tx + 16 * j] = As[0][tx + 16 * j];
    }
}

// ---------------- K3: pseudo softmax + MSE partials + adj broadcast write -----
#define TB 16
#define SC 32
__global__ void k_pseudo(const float* __restrict__ ptemp, float* __restrict__ adj_out) {
    int blk = blockIdx.x;              // 128 blocks = 4 batches x 32 row tiles
    int b = blk >> 5;
    int r0 = (blk & 31) * TB;
    int tid = threadIdx.x;             // 256 threads

    __shared__ float a_sh[TT];
    __shared__ float pt[TB][51];
    __shared__ float sb[SC][51];
    __shared__ float ps[TB][TT];
    __shared__ float sred[8];

    // recompute adjacency row a[b,:] (same fixed order as k_gemm_agg)
    float bmax, bsum, v0, v1;
    softmax_stats(b, tid, sred, bmax, bsum, v0, v1);
    float inv_bs = 1.f / bsum;
    a_sh[tid]       = __expf((v0 - bmax) * SCALE) * inv_bs;
    a_sh[tid + 256] = __expf((v1 - bmax) * SCALE) * inv_bs;

    for (int i = tid; i < TB * NC; i += 256) {
        int r = i / NC, c = i % NC;
        pt[r][c] = g_pn[(b * TT + r0 + r) * NC + c];
    }
    __syncthreads();

    for (int s0 = 0; s0 < TT; s0 += SC) {
        for (int i = tid; i < SC * NC; i += 256) {
            int s = i / NC, c = i % NC;
            sb[s][c] = g_pn[(b * TT + s0 + s) * NC + c];
        }
        __syncthreads();
        #pragma unroll
        for (int p = tid; p < TB * SC; p += 256) {
            int r = p >> 5, s = p & 31;   // warp shares r -> pt broadcast
            float acc = 0.f;
            #pragma unroll
            for (int c = 0; c < NC; c++) acc += pt[r][c] * sb[s][c];
            ps[r][s0 + s] = acc;
        }
        __syncthreads();
    }

    float invtemp = 1.f / fmaxf(fabsf(ptemp[0]), 0.01f);
    int wid = tid >> 5, lane = tid & 31;
    float lacc = 0.f;
    #pragma unroll
    for (int rr = 0; rr < 2; rr++) {
        int r = wid * 2 + rr;
        float m = -1e30f;
        for (int i = lane; i < TT; i += 32) m = fmaxf(m, ps[r][i] * invtemp);
        #pragma unroll
        for (int o = 16; o; o >>= 1) m = fmaxf(m, __shfl_xor_sync(0xffffffffu, m, o));
        float ssum = 0.f;
        for (int i = lane; i < TT; i += 32) {
            float e = __expf(ps[r][i] * invtemp - m);
            ps[r][i] = e;
            ssum += e;
        }
        #pragma unroll
        for (int o = 16; o; o >>= 1) ssum += __shfl_xor_sync(0xffffffffu, ssum, o);
        float inv = 1.f / ssum;
        for (int i = lane; i < TT; i += 32) {
            float d = ps[r][i] * inv - a_sh[i];
            lacc += d * d;
        }
    }
    #pragma unroll
    for (int o = 16; o; o >>= 1) lacc += __shfl_xor_sync(0xffffffffu, lacc, o);
    __syncthreads();
    if (lane == 0) sred[wid] = lacc;
    __syncthreads();
    if (tid == 0) {
        float s = 0.f;
        #pragma unroll
        for (int i = 0; i < 8; i++) s += sred[i];
        g_losspart[blk] = s;
    }
    // adj output: every row of this tile equals a_sh (rank-1 logits). float4 stores.
    {
        const float4* a4 = (const float4*)a_sh;
        float4* out4 = (float4*)(adj_out + (b * TT + r0) * TT);
        for (int i = tid; i < TB * (TT / 4); i += 256) {
            int r = i >> 7, c = i & 127;
            out4[r * (TT / 4) + c] = a4[c];
        }
    }
}

// ---------------- K4: h2 = g@W2^T + b2 (blocks 0-3) + loss finalize (block 4) -
__global__ void k_h2loss(const float* __restrict__ W2, const float* __restrict__ b2,
                         const float* __restrict__ supw, float* __restrict__ loss_out) {
    int tid = threadIdx.x;  // 128
    if (blockIdx.x == 4) {
        __shared__ float red[4];
        float v = g_losspart[tid];
        #pragma unroll
        for (int o = 16; o; o >>= 1) v += __shfl_xor_sync(0xffffffffu, v, o);
        if ((tid & 31) == 0) red[tid >> 5] = v;
        __syncthreads();
        if (tid == 0) {
            float total = red[0] + red[1] + red[2] + red[3];
            float mse = total * (1.f / (float)(BB * TT * TT));
            float sig = 1.f / (1.f + __expf(-supw[0]));
            loss_out[0] = mse * sig;
        }
        return;
    }
    int b = blockIdx.x;
    __shared__ float g[HH];
    for (int k = tid; k < HH; k += 128) {
        float s = 0.f;
        #pragma unroll
        for (int mt = 0; mt < 8; mt++) s += g_gpart[(b * 8 + mt) * HH + k];
        g[k] = s;
    }
    __syncthreads();
    float acc = b2[tid];
    const float* w = W2 + tid * HH;
    #pragma unroll 8
    for (int k = 0; k < HH; k++) acc += g[k] * w[k];
    g_h2[b * CC + tid] = acc;
}

// ---------------- K5: y = h2[b] + x, LayerNorm, write out ---------------------
__global__ void k_epi(const float* __restrict__ x, const float* __restrict__ gamma,
                      const float* __restrict__ beta, float* __restrict__ out) {
    int row = blockIdx.x, j = threadIdx.x;  // 2048 x 128
    int b = row >> 9;
    __shared__ float red[4];
    float y = g_h2[b * CC + j] + x[row * CC + j];
    float s = y;
    #pragma unroll
    for (int o = 16; o; o >>= 1) s += __shfl_xor_sync(0xffffffffu, s, o);
    if ((j & 31) == 0) red[j >> 5] = s;
    __syncthreads();
    float mu = (red[0] + red[1] + red[2] + red[3]) * (1.f / 128.f);
    float d = y - mu;
    __syncthreads();
    float s2 = d * d;
    #pragma unroll
    for (int o = 16; o; o >>= 1) s2 += __shfl_xor_sync(0xffffffffu, s2, o);
    if ((j & 31) == 0) red[j >> 5] = s2;
    __syncthreads();
    float var = (red[0] + red[1] + red[2] + red[3]) * (1.f / 128.f);
    out[row * CC + j] = d * rsqrtf(var + 1e-5f) * gamma[j] + beta[j];
}

// ---------------- launch ------------------------------------------------------
extern "C" void kernel_launch(void* const* d_in, const int* in_sizes, int n_in,
                              void* d_out, int out_size) {
    const float* x     = (const float*)d_in[0];
    const float* pl    = (const float*)d_in[1];
    const float* W1    = (const float*)d_in[2];
    const float* b1    = (const float*)d_in[3];
    const float* W2    = (const float*)d_in[4];
    const float* b2    = (const float*)d_in[5];
    const float* w_adj = (const float*)d_in[6];
    // d_in[7] = b_adj: cancels inside the row softmax (rank-1 logits), unused
    const float* ptemp = (const float*)d_in[8];
    const float* supw  = (const float*)d_in[9];
    const float* gamma = (const float*)d_in[10];
    const float* beta  = (const float*)d_in[11];

    float* out      = (float*)d_out;
    float* adj_out  = out + BB * TT * CC;                 // 262144
    float* loss_out = adj_out + BB * TT * TT;             // +1048576

    k_prep<<<ROWS, 128>>>(x, pl, w_adj);
    k_gemm_agg<<<dim3(32, 4), 256>>>(x, W1, b1);
    k_pseudo<<<128, 256>>>(ptemp, adj_out);
    k_h2loss<<<5, 128>>>(W2, b2, supw, loss_out);
    k_epi<<<ROWS, CC>>>(x, gamma, beta, out);
}

// round 4
// speedup vs baseline: 1.3521x; 1.3165x over previous
#include <cuda_runtime.h>
#include <cuda_bf16.h>

// Problem constants
#define BB 4
#define TT 512
#define CC 128     // IN_DIM / OUT_DIM
#define HH 256     // HIDDEN_DIM
#define NC 50      // NCLS
#define SCALE 0.0625f   // HIDDEN_DIM^-0.5
#define ROWS (BB*TT)    // 2048

// ---------------- scratch (device globals; no allocation allowed) -------------
__device__ float g_sj[ROWS];            // s_j per (b,s)
__device__ float g_pn[ROWS * NC];       // normalized pseudo labels
__device__ float g_gpart[BB * 8 * HH];  // per-(batch,mtile) partial aggregations
__device__ float g_h2[BB * CC];         // per-batch h2 = g@W2^T + b2
__device__ float g_losspart[128];       // per-block loss partials

// ---------------- K1: s_j + pseudo-label normalization ------------------------
__global__ void k_prep(const float* __restrict__ x, const float* __restrict__ pl,
                       const float* __restrict__ w_adj) {
    int row = blockIdx.x;
    int tid = threadIdx.x;   // 128 threads
    __shared__ float red[4];
    __shared__ float red2[4];

    float xv = x[row * CC + tid];
    float part = xv * w_adj[CC + tid];   // second half of w_adj
    #pragma unroll
    for (int o = 16; o; o >>= 1) part += __shfl_xor_sync(0xffffffffu, part, o);
    if ((tid & 31) == 0) red[tid >> 5] = part;

    float sq = 0.f, pv = 0.f;
    if (tid < NC) { pv = pl[row * NC + tid]; sq = pv * pv; }
    float s2 = sq;
    #pragma unroll
    for (int o = 16; o; o >>= 1) s2 += __shfl_xor_sync(0xffffffffu, s2, o);
    if ((tid & 31) == 0) red2[tid >> 5] = s2;
    __syncthreads();

    if (tid == 0) g_sj[row] = red[0] + red[1] + red[2] + red[3];
    if (tid < NC) {
        float norm = sqrtf(red2[0] + red2[1] + red2[2] + red2[3]);
        float inv = 1.f / fmaxf(norm, 1e-12f);
        g_pn[row * NC + tid] = pv * inv;
    }
}

// ------- in-block softmax helper: stats over g_sj[b*TT .. +512), 256 threads --
__device__ __forceinline__ void softmax_stats(int b, int tid, float* sred,
                                              float& bmax, float& bsum,
                                              float& v0, float& v1) {
    int lane = tid & 31, wid = tid >> 5;
    v0 = g_sj[b * TT + tid];
    v1 = g_sj[b * TT + 256 + tid];
    float m = fmaxf(v0, v1);
    #pragma unroll
    for (int o = 16; o; o >>= 1) m = fmaxf(m, __shfl_xor_sync(0xffffffffu, m, o));
    if (lane == 0) sred[wid] = m;
    __syncthreads();
    bmax = sred[0];
    #pragma unroll
    for (int i = 1; i < 8; i++) bmax = fmaxf(bmax, sred[i]);
    __syncthreads();
    float e = __expf((v0 - bmax) * SCALE) + __expf((v1 - bmax) * SCALE);
    #pragma unroll
    for (int o = 16; o; o >>= 1) e += __shfl_xor_sync(0xffffffffu, e, o);
    if (lane == 0) sred[wid] = e;
    __syncthreads();
    bsum = 0.f;
    #pragma unroll
    for (int i = 0; i < 8; i++) bsum += sred[i];
    __syncthreads();
}

// ---------------- K2: fused h-GEMM + a-weighted aggregation -------------------
// grid (32 mtiles, 4 ntiles) x 256 thr. Each block: 64 rows x 64 cols of
// h = relu(x@W1^T + b1), then reduces sum_m a[m]*h[m,n] -> g_gpart.
__global__ void k_gemm_agg(const float* __restrict__ x, const float* __restrict__ W1,
                           const float* __restrict__ b1) {
    __shared__ float As[16][65];
    __shared__ float Bs[16][65];
    __shared__ float sred[8];
    __shared__ float a_sh[64];

    int mt = blockIdx.x;       // global 64-row tile, 0..31
    int b  = mt >> 3;
    int m0 = mt * 64;
    int n0 = blockIdx.y * 64;
    int tid = threadIdx.x;
    int ty = tid >> 4, tx = tid & 15;

    // recompute softmax over this batch (fixed order => deterministic)
    float bmax, bsum, v0, v1;
    softmax_stats(b, tid, sred, bmax, bsum, v0, v1);
    if (tid < 64) a_sh[tid] = __expf((g_sj[m0 + tid] - bmax) * SCALE) / bsum;
    // (a_sh consumed only after the k-loop's __syncthreads barriers)

    float c[4][4] = {};
    for (int k0 = 0; k0 < CC; k0 += 16) {
        int kk = tid & 15, rr = tid >> 4;
        #pragma unroll
        for (int i = 0; i < 4; i++) {
            As[kk][rr + 16 * i] = x[(m0 + rr + 16 * i) * CC + k0 + kk];
            Bs[kk][rr + 16 * i] = W1[(n0 + rr + 16 * i) * CC + k0 + kk];
        }
        __syncthreads();
        #pragma unroll
        for (int k = 0; k < 16; k++) {
            float av[4], bv[4];
            #pragma unroll
            for (int i = 0; i < 4; i++) { av[i] = As[k][ty + 16 * i]; bv[i] = Bs[k][tx + 16 * i]; }
            #pragma unroll
            for (int i = 0; i < 4; i++)
                #pragma unroll
                for (int j = 0; j < 4; j++) c[i][j] += av[i] * bv[j];
        }
        __syncthreads();
    }

    // epilogue: gl[j] = sum_i a[m] * relu(c + b1)
    float b1v[4], gl[4] = {};
    #pragma unroll
    for (int j = 0; j < 4; j++) b1v[j] = b1[n0 + tx + 16 * j];
    #pragma unroll
    for (int i = 0; i < 4; i++) {
        float av = a_sh[ty + 16 * i];
        #pragma unroll
        for (int j = 0; j < 4; j++)
            gl[j] += av * fmaxf(c[i][j] + b1v[j], 0.f);
    }
    // reduce over ty (16 groups), reusing As
    #pragma unroll
    for (int j = 0; j < 4; j++) As[ty][tx + 16 * j] = gl[j];
    __syncthreads();
    #pragma unroll
    for (int st = 8; st; st >>= 1) {
        if (ty < st) {
            #pragma unroll
            for (int j = 0; j < 4; j++) As[ty][tx + 16 * j] += As[ty + st][tx + 16 * j];
        }
        __syncthreads();
    }
    if (ty == 0) {
        #pragma unroll
        for (int j = 0; j < 4; j++)
            g_gpart[mt * HH + n0 + tx + 16 * j] = As[0][tx + 16 * j];
    }
}

// ---------------- K3: pseudo softmax + MSE + adj write; blocks 128-131: h2 ----
#define TB 16
#define SC 32
__global__ void k_pseudo(const float* __restrict__ ptemp, float* __restrict__ adj_out,
                         const float* __restrict__ W2, const float* __restrict__ b2) {
    int blk = blockIdx.x;              // 0-127 pseudo; 128-131 h2 per batch
    int tid = threadIdx.x;             // 256 threads

    if (blk >= 128) {
        // ---- h2[b,:] = g[b,:] @ W2^T + b2, coalesced warp-per-output ----
        int b = blk - 128;
        __shared__ float g[HH];
        for (int k = tid; k < HH; k += 256) {
            float s = 0.f;
            #pragma unroll
            for (int mt = 0; mt < 8; mt++) s += g_gpart[(b * 8 + mt) * HH + k];
            g[k] = s;
        }
        __syncthreads();
        int wid = tid >> 5, lane = tid & 31;
        #pragma unroll
        for (int jj = 0; jj < 16; jj++) {
            int j = wid * 16 + jj;                    // output channel 0..127
            const float* w = W2 + j * HH;
            float acc = 0.f;
            #pragma unroll
            for (int i = 0; i < 8; i++)
                acc += g[lane + 32 * i] * __ldg(w + lane + 32 * i);  // coalesced
            #pragma unroll
            for (int o = 16; o; o >>= 1) acc += __shfl_xor_sync(0xffffffffu, acc, o);
            if (lane == 0) g_h2[b * CC + j] = acc + b2[j];
        }
        return;
    }

    int b = blk >> 5;
    int r0 = (blk & 31) * TB;

    __shared__ float a_sh[TT];
    __shared__ float pt[TB][51];
    __shared__ float sb[SC][51];
    __shared__ float ps[TB][TT];
    __shared__ float sred[8];

    // recompute adjacency row a[b,:] (same fixed order as k_gemm_agg)
    float bmax, bsum, v0, v1;
    softmax_stats(b, tid, sred, bmax, bsum, v0, v1);
    float inv_bs = 1.f / bsum;
    a_sh[tid]       = __expf((v0 - bmax) * SCALE) * inv_bs;
    a_sh[tid + 256] = __expf((v1 - bmax) * SCALE) * inv_bs;

    for (int i = tid; i < TB * NC; i += 256) {
        int r = i / NC, c = i % NC;
        pt[r][c] = g_pn[(b * TT + r0 + r) * NC + c];
    }
    __syncthreads();

    for (int s0 = 0; s0 < TT; s0 += SC) {
        for (int i = tid; i < SC * NC; i += 256) {
            int s = i / NC, c = i % NC;
            sb[s][c] = g_pn[(b * TT + s0 + s) * NC + c];
        }
        __syncthreads();
        #pragma unroll
        for (int p = tid; p < TB * SC; p += 256) {
            int r = p >> 5, s = p & 31;   // warp shares r -> pt broadcast
            float acc = 0.f;
            #pragma unroll
            for (int c = 0; c < NC; c++) acc += pt[r][c] * sb[s][c];
            ps[r][s0 + s] = acc;
        }
        __syncthreads();
    }

    float invtemp = 1.f / fmaxf(fabsf(ptemp[0]), 0.01f);
    int wid = tid >> 5, lane = tid & 31;
    float lacc = 0.f;
    #pragma unroll
    for (int rr = 0; rr < 2; rr++) {
        int r = wid * 2 + rr;
        float m = -1e30f;
        for (int i = lane; i < TT; i += 32) m = fmaxf(m, ps[r][i] * invtemp);
        #pragma unroll
        for (int o = 16; o; o >>= 1) m = fmaxf(m, __shfl_xor_sync(0xffffffffu, m, o));
        float ssum = 0.f;
        for (int i = lane; i < TT; i += 32) {
            float e = __expf(ps[r][i] * invtemp - m);
            ps[r][i] = e;
            ssum += e;
        }
        #pragma unroll
        for (int o = 16; o; o >>= 1) ssum += __shfl_xor_sync(0xffffffffu, ssum, o);
        float inv = 1.f / ssum;
        for (int i = lane; i < TT; i += 32) {
            float d = ps[r][i] * inv - a_sh[i];
            lacc += d * d;
        }
    }
    #pragma unroll
    for (int o = 16; o; o >>= 1) lacc += __shfl_xor_sync(0xffffffffu, lacc, o);
    __syncthreads();
    if (lane == 0) sred[wid] = lacc;
    __syncthreads();
    if (tid == 0) {
        float s = 0.f;
        #pragma unroll
        for (int i = 0; i < 8; i++) s += sred[i];
        g_losspart[blk] = s;
    }
    // adj output: every row of this tile equals a_sh (rank-1 logits). float4 stores.
    {
        const float4* a4 = (const float4*)a_sh;
        float4* out4 = (float4*)(adj_out + (b * TT + r0) * TT);
        for (int i = tid; i < TB * (TT / 4); i += 256) {
            int r = i >> 7, c = i & 127;
            out4[r * (TT / 4) + c] = a4[c];
        }
    }
}

// ---------------- K4: y = h2[b]+x, LayerNorm (blocks 0-2047); loss (block 2048)
__global__ void k_epi(const float* __restrict__ x, const float* __restrict__ gamma,
                      const float* __restrict__ beta, float* __restrict__ out,
                      const float* __restrict__ supw, float* __restrict__ loss_out) {
    int row = blockIdx.x, j = threadIdx.x;  // 2049 x 128
    __shared__ float red[4];
    if (row == ROWS) {
        float v = g_losspart[j];
        #pragma unroll
        for (int o = 16; o; o >>= 1) v += __shfl_xor_sync(0xffffffffu, v, o);
        if ((j & 31) == 0) red[j >> 5] = v;
        __syncthreads();
        if (j == 0) {
            float total = red[0] + red[1] + red[2] + red[3];
            float mse = total * (1.f / (float)(BB * TT * TT));
            float sig = 1.f / (1.f + __expf(-supw[0]));
            loss_out[0] = mse * sig;
        }
        return;
    }
    int b = row >> 9;
    float y = g_h2[b * CC + j] + x[row * CC + j];
    float s = y;
    #pragma unroll
    for (int o = 16; o; o >>= 1) s += __shfl_xor_sync(0xffffffffu, s, o);
    if ((j & 31) == 0) red[j >> 5] = s;
    __syncthreads();
    float mu = (red[0] + red[1] + red[2] + red[3]) * (1.f / 128.f);
    float d = y - mu;
    __syncthreads();
    float s2 = d * d;
    #pragma unroll
    for (int o = 16; o; o >>= 1) s2 += __shfl_xor_sync(0xffffffffu, s2, o);
    if ((j & 31) == 0) red[j >> 5] = s2;
    __syncthreads();
    float var = (red[0] + red[1] + red[2] + red[3]) * (1.f / 128.f);
    out[row * CC + j] = d * rsqrtf(var + 1e-5f) * gamma[j] + beta[j];
}

// ---------------- launch ------------------------------------------------------
extern "C" void kernel_launch(void* const* d_in, const int* in_sizes, int n_in,
                              void* d_out, int out_size) {
    const float* x     = (const float*)d_in[0];
    const float* pl    = (const float*)d_in[1];
    const float* W1    = (const float*)d_in[2];
    const float* b1    = (const float*)d_in[3];
    const float* W2    = (const float*)d_in[4];
    const float* b2    = (const float*)d_in[5];
    const float* w_adj = (const float*)d_in[6];
    // d_in[7] = b_adj: cancels inside the row softmax (rank-1 logits), unused
    const float* ptemp = (const float*)d_in[8];
    const float* supw  = (const float*)d_in[9];
    const float* gamma = (const float*)d_in[10];
    const float* beta  = (const float*)d_in[11];

    float* out      = (float*)d_out;
    float* adj_out  = out + BB * TT * CC;                 // 262144
    float* loss_out = adj_out + BB * TT * TT;             // +1048576

    k_prep<<<ROWS, 128>>>(x, pl, w_adj);
    k_gemm_agg<<<dim3(32, 4), 256>>>(x, W1, b1);
    k_pseudo<<<132, 256>>>(ptemp, adj_out, W2, b2);
    k_epi<<<ROWS + 1, 128>>>(x, gamma, beta, out, supw, loss_out);
}